// round 13
// baseline (speedup 1.0000x reference)
#include <cuda_runtime.h>
#include <cuda_bf16.h>
#include <cuda_fp16.h>
#include <cstdint>
#include <math.h>

// Problem constants
constexpr int DM = 1024;   // d_model
constexpr int H  = 16;     // heads
constexpr int DH = 64;     // head dim
constexpr int B  = 4;      // batch
constexpr int S  = 2048;   // seq len
constexpr int M  = B * S;  // 8192 rows

// Scratch (allocation-free rule: __device__ globals)
__device__ __half g_xh[(size_t)M * DM];                // x, fp16 RN
__device__ __half g_whi[(size_t)4 * DM * DM];          // weights, fp16 RN
__device__ __half g_qkvh[(size_t)3 * M * DM];          // q,k,v head-major fp16
__device__ __half g_aoh[(size_t)M * DM];               // attention out, fp16 RN

// ---------------------------------------------------------------------------
// PTX helpers (compute_103-safe)
// ---------------------------------------------------------------------------
__device__ __forceinline__ uint32_t smem_u32(const void* p) {
    uint32_t a;
    asm("{ .reg .u64 t; cvta.to.shared.u64 t, %1; cvt.u32.u64 %0, t; }"
        : "=r"(a) : "l"(p));
    return a;
}
__device__ __forceinline__ void cp16(uint32_t saddr, const void* gaddr) {
    asm volatile("cp.async.cg.shared.global [%0], [%1], 16;"
                 :: "r"(saddr), "l"(gaddr) : "memory");
}
__device__ __forceinline__ void cp_commit() {
    asm volatile("cp.async.commit_group;" ::: "memory");
}
template <int N>
__device__ __forceinline__ void cp_waitg() {
    asm volatile("cp.async.wait_group %0;" :: "n"(N) : "memory");
}
__device__ __forceinline__ void ldsm4(uint32_t* r, uint32_t addr) {
    asm volatile("ldmatrix.sync.aligned.m8n8.x4.shared.b16 {%0,%1,%2,%3}, [%4];"
                 : "=r"(r[0]), "=r"(r[1]), "=r"(r[2]), "=r"(r[3]) : "r"(addr));
}
__device__ __forceinline__ void ldsm4t(uint32_t* r, uint32_t addr) {
    asm volatile("ldmatrix.sync.aligned.m8n8.x4.trans.shared.b16 {%0,%1,%2,%3}, [%4];"
                 : "=r"(r[0]), "=r"(r[1]), "=r"(r[2]), "=r"(r[3]) : "r"(addr));
}
// fp16 mma
__device__ __forceinline__ void mma16816h(float* c, const uint32_t* a, const uint32_t* b) {
    asm volatile(
        "mma.sync.aligned.m16n8k16.row.col.f32.f16.f16.f32 "
        "{%0,%1,%2,%3}, {%4,%5,%6,%7}, {%8,%9}, {%0,%1,%2,%3};"
        : "+f"(c[0]), "+f"(c[1]), "+f"(c[2]), "+f"(c[3])
        : "r"(a[0]), "r"(a[1]), "r"(a[2]), "r"(a[3]), "r"(b[0]), "r"(b[1]));
}
// fp16 RN pack (a -> low half)
__device__ __forceinline__ uint32_t pkh2(float a, float b) {
    uint32_t r;
    asm("cvt.rn.f16x2.f32 %0, %1, %2;" : "=r"(r) : "f"(b), "f"(a));
    return r;
}

// ---------------------------------------------------------------------------
// Merged split, 4-way MLP: x -> fp16 RN, 4 weights -> fp16 RN.
// ---------------------------------------------------------------------------
constexpr int XN4 = (M * DM) / 4;     // 2M float4
constexpr int WN4 = (DM * DM) / 4;    // 256K float4
constexpr int SPLIT_TOTAL = XN4 + 4 * WN4;
constexpr int SPLIT_STRIDE = (SPLIT_TOTAL + 3) / 4;

__global__ __launch_bounds__(256) void split_all(
    const float4* __restrict__ x,
    const float4* __restrict__ w0, const float4* __restrict__ w1,
    const float4* __restrict__ w2, const float4* __restrict__ w3,
    uint32_t* __restrict__ xh, uint32_t* __restrict__ whi) {
    const int base = blockIdx.x * 256 + threadIdx.x;
    const float4* ws[4] = {w0, w1, w2, w3};
    float4 v[4];
    int idx[4];
#pragma unroll
    for (int k = 0; k < 4; k++) {
        int i = base + k * SPLIT_STRIDE;
        idx[k] = i;
        if (i < SPLIT_TOTAL) {
            v[k] = (i < XN4) ? x[i] : ws[(i - XN4) >> 18][(i - XN4) & (WN4 - 1)];
        }
    }
#pragma unroll
    for (int k = 0; k < 4; k++) {
        int i = idx[k];
        if (i >= SPLIT_TOTAL) continue;
        uint32_t p0 = pkh2(v[k].x, v[k].y);
        uint32_t p1 = pkh2(v[k].z, v[k].w);
        if (i < XN4) {
            xh[2 * i] = p0;
            xh[2 * i + 1] = p1;
        } else {
            int j = i - XN4;
            size_t o = (size_t)(j >> 18) * (2 * WN4) + 2 * (j & (WN4 - 1));
            whi[o] = p0;
            whi[o + 1] = p1;
        }
    }
}

// ---------------------------------------------------------------------------
// fp16 single-term GEMM: C[M,N] = Ah[M,K] @ Wh[N,K]^T, fp32 accumulate.
// BM=64 BN=128 BK=32, 128 thr (4 warps, 2x2, warp tile 32x64).
// 3-stage cp.async pipeline, one barrier per k-iter, 4 CTAs/SM.
// OUTBF=1: fused QKV (grid.x=24, widx=bn>>3), fp16 RN head-major out.
// ---------------------------------------------------------------------------
constexpr int ROWB = 80;
constexpr int TILEA = 64 * ROWB;             // 5120
constexpr int TILEW = 128 * ROWB;            // 10240
constexpr int NSTG = 3;
constexpr int A_REG = NSTG * TILEA;          // 15360
constexpr int GEMM_SMEM = A_REG + NSTG * TILEW;  // 46080
constexpr int NKT = DM / 32;

template <int OUTBF>
__global__ __launch_bounds__(128) void gemm_f16(const __half* __restrict__ Ah,
                                                const __half* __restrict__ Wh,
                                                float* __restrict__ C,
                                                __half* __restrict__ QKVh) {
    extern __shared__ char smem[];
    const uint32_t sb = smem_u32(smem);
    const int tid = threadIdx.x;
    const int lane = tid & 31;
    const int wid = tid >> 5;           // 0..3
    const int warpM = wid & 1;          // 0..1 -> 32 rows each
    const int warpN = wid >> 1;         // 0..1 -> 64 cols each
    const int bn = blockIdx.x;
    const int bm = blockIdx.y;
    const int widx = (OUTBF == 1) ? (bn >> 3) : 0;
    const int bnl = (OUTBF == 1) ? (bn & 7) : bn;
    const int rowA0 = bm * 64;
    const int rowB0 = bnl * 128;
    const __half* Bh = Wh + (size_t)widx * DM * DM;

    const uint32_t so_c = (uint32_t)((tid & 3) * 16);
    const int lc = (tid & 3) * 8;

    auto load_stage = [&](int kt, int buf) {
        const size_t gkoff = (size_t)kt * 32 + lc;
        uint32_t abase = sb + buf * TILEA;
        uint32_t bbase = sb + A_REG + buf * TILEW;
#pragma unroll
        for (int i = 0; i < 2; i++) {       // A: 64 rows
            int r = (tid + i * 128) >> 2;
            cp16(abase + (uint32_t)(r * ROWB) + so_c,
                 Ah + (size_t)(rowA0 + r) * DM + gkoff);
        }
#pragma unroll
        for (int i = 0; i < 4; i++) {       // B: 128 rows
            int r = (tid + i * 128) >> 2;
            cp16(bbase + (uint32_t)(r * ROWB) + so_c,
                 Bh + (size_t)(rowB0 + r) * DM + gkoff);
        }
        cp_commit();
    };

    float acc[2][8][4];
#pragma unroll
    for (int i = 0; i < 2; i++)
#pragma unroll
        for (int j = 0; j < 8; j++)
#pragma unroll
            for (int e = 0; e < 4; e++) acc[i][j][e] = 0.f;

    load_stage(0, 0);
    load_stage(1, 1);

    const int a_r = (lane & 15);
    const int a_c8 = (lane >> 4) * 8;
    const int b_r = ((lane >> 4) * 8) + (lane & 7);
    const int b_c8 = ((lane >> 3) & 1) * 8;

    for (int kt = 0; kt < NKT; kt++) {
        const int buf = kt % 3;
        cp_waitg<1>();
        __syncthreads();   // data(kt) visible AND compute(kt-1) done

        int ktn = kt + 2;
        if (ktn > NKT - 1) ktn = NKT - 1;
        load_stage(ktn, (kt + 2) % 3);

        const uint32_t aHi = sb + buf * TILEA;
        const uint32_t bHi = sb + A_REG + buf * TILEW;
        const int mrow = warpM * 32 + a_r;
        const int nrow0 = warpN * 64 + b_r;

#pragma unroll
        for (int ks = 0; ks < 2; ks++) {
            uint32_t ah[2][4], bh[4][4];
            const uint32_t acol = (uint32_t)((ks * 16 + a_c8) * 2);
            const uint32_t bcol = (uint32_t)((ks * 16 + b_c8) * 2);
#pragma unroll
            for (int mt = 0; mt < 2; mt++) {
                uint32_t ro = (uint32_t)((mrow + mt * 16) * ROWB) + acol;
                ldsm4(ah[mt], aHi + ro);
            }
#pragma unroll
            for (int np = 0; np < 4; np++) {
                uint32_t ro = (uint32_t)((nrow0 + np * 16) * ROWB) + bcol;
                ldsm4(bh[np], bHi + ro);
            }
#pragma unroll
            for (int mt = 0; mt < 2; mt++)
#pragma unroll
                for (int np = 0; np < 4; np++)
#pragma unroll
                    for (int ns = 0; ns < 2; ns++)
                        mma16816h(acc[mt][np * 2 + ns], ah[mt], &bh[np][ns * 2]);
        }
    }

    const int rbase = bm * 64 + warpM * 32 + (lane >> 2);
    const int cbase = bnl * 128 + warpN * 64 + (lane & 3) * 2;
    __half* Chi = QKVh + (size_t)widx * M * DM;
#pragma unroll
    for (int mt = 0; mt < 2; mt++) {
#pragma unroll
        for (int nt = 0; nt < 8; nt++) {
            int row = rbase + mt * 16;
            int col = cbase + nt * 8;
#pragma unroll
            for (int half = 0; half < 2; half++) {
                int r = row + half * 8;
                float vx = acc[mt][nt][half * 2];
                float vy = acc[mt][nt][half * 2 + 1];
                if (OUTBF == 0) {
                    *(float2*)(C + (size_t)r * DM + col) = make_float2(vx, vy);
                } else {
                    int b_ = r >> 11;
                    int s_ = r & 2047;
                    int h_ = col >> 6;
                    int d_ = col & 63;
                    size_t idx = ((((size_t)b_ * H + h_) * S + s_) << 6) + d_;
                    *(uint32_t*)(Chi + idx) = pkh2(vx, vy);
                }
            }
        }
    }
}

// ---------------------------------------------------------------------------
// Tensor-core causal flash attention (unchanged from R12: fully fp16
// single-term, fp32 softmax/accumulate, 128 thr, 64 queries/CTA).
// ---------------------------------------------------------------------------
constexpr int AROWB = 144;
constexpr int ATILE = 64 * AROWB;       // 9216
constexpr int ASTG = 2 * ATILE;         // K, V
constexpr int ATT_SMEM = 2 * ASTG;      // 36864
constexpr float SC2 = 0.125f * 1.4426950408889634f;  // (1/sqrt(64)) * log2(e)

__global__ __launch_bounds__(128) void attn_mma(
    const __half* __restrict__ QKVh, __half* __restrict__ AOh) {
    extern __shared__ char smem[];
    const uint32_t sb = smem_u32(smem);
    const int tid = threadIdx.x;
    const int lane = tid & 31;
    const int wid = tid >> 5;
    const int qt = (int)gridDim.x - 1 - (int)blockIdx.x;  // longest first
    const int h = blockIdx.y;
    const int b = blockIdx.z;
    const size_t hb = (((size_t)b * H + h) * S) * DH;
    const __half* Qh = QKVh;
    const __half* Kh = QKVh + (size_t)M * DM;
    const __half* Vh = QKVh + (size_t)2 * M * DM;

    // Stage Q (64x64) into buffer 0's first tile, extract to regs
#pragma unroll
    for (int i = 0; i < 4; i++) {
        int id = tid + i * 128;
        if (id < 512) {
            int r = id >> 3, c = id & 7;
            uint32_t so = (uint32_t)(r * AROWB + c * 16);
            size_t g = hb + (size_t)(qt * 64 + r) * DH + c * 8;
            cp16(sb + so, Qh + g);
        }
    }
    cp_commit();
    cp_waitg<0>();
    __syncthreads();

    uint32_t qh[4][4];
    {
        int row = wid * 16 + (lane & 15);
#pragma unroll
        for (int ks = 0; ks < 4; ks++) {
            uint32_t off = (uint32_t)(row * AROWB + (ks * 16 + (lane >> 4) * 8) * 2);
            ldsm4(qh[ks], sb + off);
        }
    }
    __syncthreads();

    float ov[8][4];
#pragma unroll
    for (int o = 0; o < 8; o++)
#pragma unroll
        for (int e = 0; e < 4; e++) ov[o][e] = 0.f;
    float m0 = -1e30f, m1 = -1e30f, l0 = 0.f, l1 = 0.f;

    const int nkt = qt + 1;

    auto load_kv = [&](int kt, int bufi) {
        uint32_t base = sb + bufi * ASTG;
#pragma unroll
        for (int i = 0; i < 4; i++) {
            int id = tid + i * 128;
            int r = id >> 3, c = id & 7;
            uint32_t so = (uint32_t)(r * AROWB + c * 16);
            size_t g = hb + (size_t)(kt * 64 + r) * DH + c * 8;
            cp16(base + so,         Kh + g);
            cp16(base + ATILE + so, Vh + g);
        }
        cp_commit();
    };
    load_kv(0, 0);

    const int q0 = qt * 64 + wid * 16 + (lane >> 2);
    const int q1 = q0 + 8;

    for (int kt = 0; kt < nkt; kt++) {
        const int buf = kt & 1;
        cp_waitg<0>();
        __syncthreads();

        if (kt + 1 < nkt) load_kv(kt + 1, buf ^ 1);

        const uint32_t kb = sb + buf * ASTG;

        // S = Q * K
        float sf[8][4];
#pragma unroll
        for (int o = 0; o < 8; o++)
#pragma unroll
            for (int e = 0; e < 4; e++) sf[o][e] = 0.f;

#pragma unroll
        for (int ks = 0; ks < 4; ks++) {
#pragma unroll
            for (int np = 0; np < 4; np++) {
                uint32_t kh4[4];
                uint32_t ro = (uint32_t)(
                    (np * 16 + (lane >> 4) * 8 + (lane & 7)) * AROWB +
                    (ks * 16 + ((lane >> 3) & 1) * 8) * 2);
                ldsm4(kh4, kb + ro);
#pragma unroll
                for (int ns = 0; ns < 2; ns++)
                    mma16816h(sf[np * 2 + ns], qh[ks], &kh4[ns * 2]);
            }
        }

        // online softmax in exp2 domain
        const bool diag = (kt == qt);
        float mx0 = -1e30f, mx1 = -1e30f;
#pragma unroll
        for (int o = 0; o < 8; o++) {
#pragma unroll
            for (int e = 0; e < 2; e++) {
                int keyl = o * 8 + (lane & 3) * 2 + e;
                float v0 = sf[o][e] * SC2;
                float v1 = sf[o][2 + e] * SC2;
                if (diag && keyl > q0 - qt * 64) v0 = -1e30f;
                if (diag && keyl > q1 - qt * 64) v1 = -1e30f;
                sf[o][e] = v0;
                sf[o][2 + e] = v1;
                mx0 = fmaxf(mx0, v0);
                mx1 = fmaxf(mx1, v1);
            }
        }
        mx0 = fmaxf(mx0, __shfl_xor_sync(0xffffffffu, mx0, 1));
        mx0 = fmaxf(mx0, __shfl_xor_sync(0xffffffffu, mx0, 2));
        mx1 = fmaxf(mx1, __shfl_xor_sync(0xffffffffu, mx1, 1));
        mx1 = fmaxf(mx1, __shfl_xor_sync(0xffffffffu, mx1, 2));
        const float mn0 = fmaxf(m0, mx0);
        const float mn1 = fmaxf(m1, mx1);
        const float es0 = exp2f(m0 - mn0);
        const float es1 = exp2f(m1 - mn1);
        m0 = mn0; m1 = mn1;

        float rs0 = 0.f, rs1 = 0.f;
#pragma unroll
        for (int o = 0; o < 8; o++) {
#pragma unroll
            for (int e = 0; e < 2; e++) {
                float p0 = exp2f(sf[o][e] - mn0);
                float p1 = exp2f(sf[o][2 + e] - mn1);
                sf[o][e] = p0;
                sf[o][2 + e] = p1;
                rs0 += p0;
                rs1 += p1;
            }
        }
        rs0 += __shfl_xor_sync(0xffffffffu, rs0, 1);
        rs0 += __shfl_xor_sync(0xffffffffu, rs0, 2);
        rs1 += __shfl_xor_sync(0xffffffffu, rs1, 1);
        rs1 += __shfl_xor_sync(0xffffffffu, rs1, 2);
        l0 = l0 * es0 + rs0;
        l1 = l1 * es1 + rs1;
#pragma unroll
        for (int o = 0; o < 8; o++) {
            ov[o][0] *= es0; ov[o][1] *= es0;
            ov[o][2] *= es1; ov[o][3] *= es1;
        }

        // O += P * V   (P fp16 RN; V via ldmatrix.trans)
#pragma unroll
        for (int kp = 0; kp < 4; kp++) {
            uint32_t pah[4];
            pah[0] = pkh2(sf[2 * kp][0],     sf[2 * kp][1]);
            pah[1] = pkh2(sf[2 * kp][2],     sf[2 * kp][3]);
            pah[2] = pkh2(sf[2 * kp + 1][0], sf[2 * kp + 1][1]);
            pah[3] = pkh2(sf[2 * kp + 1][2], sf[2 * kp + 1][3]);
#pragma unroll
            for (int dp = 0; dp < 4; dp++) {
                uint32_t bvh[4];
                uint32_t vo = (uint32_t)(
                    (kp * 16 + (lane & 15)) * AROWB +
                    (dp * 16 + (lane >> 4) * 8) * 2);
                ldsm4t(bvh, kb + ATILE + vo);
#pragma unroll
                for (int ns = 0; ns < 2; ns++)
                    mma16816h(ov[dp * 2 + ns], pah, &bvh[ns * 2]);
            }
        }
    }

    // epilogue: normalize, fp16 RN, write [b, s, h*64 + d]
    const float inv0 = 1.f / l0;
    const float inv1 = 1.f / l1;
    const int s0 = qt * 64 + wid * 16 + (lane >> 2);
    const size_t row0 = ((size_t)b * S + s0) * DM + h * DH;
    const size_t row1 = row0 + (size_t)8 * DM;
#pragma unroll
    for (int o = 0; o < 8; o++) {
        int d = o * 8 + (lane & 3) * 2;
        *(uint32_t*)(AOh + row0 + d) = pkh2(ov[o][0] * inv0, ov[o][1] * inv0);
        *(uint32_t*)(AOh + row1 + d) = pkh2(ov[o][2] * inv1, ov[o][3] * inv1);
    }
}

// ---------------------------------------------------------------------------
extern "C" void kernel_launch(void* const* d_in, const int* in_sizes, int n_in,
                              void* d_out, int out_size) {
    const float* w[4] = {nullptr, nullptr, nullptr, nullptr};
    const float* x = nullptr;
    int wn = 0;
    for (int i = 0; i < n_in; i++) {
        if (in_sizes[i] == DM * DM && wn < 4) {
            w[wn++] = (const float*)d_in[i];
        } else if (in_sizes[i] == B * S * DM) {
            x = (const float*)d_in[i];
        }
    }

    __half *xh, *whi, *qkvh, *aoh;
    cudaGetSymbolAddress((void**)&xh, g_xh);
    cudaGetSymbolAddress((void**)&whi, g_whi);
    cudaGetSymbolAddress((void**)&qkvh, g_qkvh);
    cudaGetSymbolAddress((void**)&aoh, g_aoh);

    cudaFuncSetAttribute(gemm_f16<0>, cudaFuncAttributeMaxDynamicSharedMemorySize, GEMM_SMEM);
    cudaFuncSetAttribute(gemm_f16<1>, cudaFuncAttributeMaxDynamicSharedMemorySize, GEMM_SMEM);
    cudaFuncSetAttribute(attn_mma, cudaFuncAttributeMaxDynamicSharedMemorySize, ATT_SMEM);

    split_all<<<(SPLIT_STRIDE + 255) / 256, 256>>>(
        (const float4*)x, (const float4*)w[0], (const float4*)w[1],
        (const float4*)w[2], (const float4*)w[3],
        (uint32_t*)xh, (uint32_t*)whi);

    dim3 qkvgrid(3 * DM / 128, M / 64);   // (24, 128)
    gemm_f16<1><<<qkvgrid, 128, GEMM_SMEM>>>(xh, whi, nullptr, qkvh);

    dim3 agrid(S / 64, H, B);  // (32, 16, 4)
    attn_mma<<<agrid, 128, ATT_SMEM>>>(qkvh, aoh);

    dim3 ogrid(DM / 128, M / 64);         // (8, 128)
    gemm_f16<0><<<ogrid, 128, GEMM_SMEM>>>(aoh, whi + (size_t)3 * DM * DM,
                                           (float*)d_out, nullptr);
}